// round 6
// baseline (speedup 1.0000x reference)
#include <cuda_runtime.h>
#include <cuda_bf16.h>
#include <stdint.h>

// Problem constants
#define B_TOT   4096
#define T_      64
#define D_      250
#define K_      1000
#define H_      125
#define NT      4
#define NL      50

// Tiling
#define BM      32
#define BN      128
#define KCH     64
#define NCHUNK  16
#define THREADS 256
#define HSS     132

// smem layout (bytes)
#define OFF_A    0                    // [buf2][hi|lo] 8192 each -> 16384
#define OFF_B    16384                // [buf2][hi/lo] 16384 each -> 65536
#define SMEM_TOTAL (OFF_B + 4*16384)  // 81920
#define OFF_HS   OFF_B                // epilogue: Hs[32][HSS] f32 = 16896
#define OFF_W2S  (OFF_B + 16896)      // W2 cache, up to 25 KB

#define SW128(x) ((x) ^ ((((uint32_t)(x)) >> 3) & 0x70))

// Pre-split, pre-swizzled W1 images: [half][hi/lo][chunk][16384B]
__device__ __align__(16) uint8_t g_wbf[(size_t)2 * 2 * 16 * 16384];
// Pre-gathered, pre-split A images: [mblk128][chunk16][hi 4096 | lo 4096]
__device__ __align__(16) uint8_t g_abf[(size_t)128 * 16 * 8192];

__device__ __forceinline__ uint32_t smem_u32(const void* p) {
    uint32_t a;
    asm("{ .reg .u64 t; cvta.to.shared.u64 t, %1; cvt.u32.u64 %0, t; }"
        : "=r"(a) : "l"(p));
    return a;
}
__device__ __forceinline__ void ldsm4(uint32_t r[4], uint32_t a) {
    asm volatile("ldmatrix.sync.aligned.m8n8.x4.shared.b16 {%0,%1,%2,%3}, [%4];"
        : "=r"(r[0]), "=r"(r[1]), "=r"(r[2]), "=r"(r[3]) : "r"(a));
}
__device__ __forceinline__ void ldsm4t(uint32_t r[4], uint32_t a) {
    asm volatile("ldmatrix.sync.aligned.m8n8.x4.trans.shared.b16 {%0,%1,%2,%3}, [%4];"
        : "=r"(r[0]), "=r"(r[1]), "=r"(r[2]), "=r"(r[3]) : "r"(a));
}
__device__ __forceinline__ void mma16816(float c[4], const uint32_t a[4],
                                         uint32_t b0, uint32_t b1) {
    asm volatile(
        "mma.sync.aligned.m16n8k16.row.col.f32.bf16.bf16.f32 "
        "{%0,%1,%2,%3}, {%4,%5,%6,%7}, {%8,%9}, {%0,%1,%2,%3};"
        : "+f"(c[0]), "+f"(c[1]), "+f"(c[2]), "+f"(c[3])
        : "r"(a[0]), "r"(a[1]), "r"(a[2]), "r"(a[3]), "r"(b0), "r"(b1));
}
__device__ __forceinline__ void cp_async16(uint32_t s, const void* g) {
    asm volatile("cp.async.cg.shared.global [%0], [%1], 16;" :: "r"(s), "l"(g) : "memory");
}
__device__ __forceinline__ void cp_commit() {
    asm volatile("cp.async.commit_group;" ::: "memory");
}
template <int N> __device__ __forceinline__ void cp_wait() {
    asm volatile("cp.async.wait_group %0;" :: "n"(N) : "memory");
}

// ------- prep W1: split into swizzled bf16 hi/lo chunk images -------
__global__ void prep_w_kernel(const float* __restrict__ W1t,
                              const float* __restrict__ W1r)
{
    int idx  = blockIdx.x * blockDim.x + threadIdx.x;   // 0..131071
    int np   = idx & 63;
    int k    = (idx >> 6) & 1023;
    int half = idx >> 16;
    const float* W1 = half ? W1r : W1t;

    int n0 = np * 2;
    float w0 = 0.f, w1 = 0.f;
    if (k < K_) {
        if (n0 < H_)     w0 = W1[k * H_ + n0];
        if (n0 + 1 < H_) w1 = W1[k * H_ + n0 + 1];
    }
    __nv_bfloat16 h0 = __float2bfloat16(w0);
    __nv_bfloat16 h1 = __float2bfloat16(w1);
    __nv_bfloat16 l0 = __float2bfloat16(w0 - __bfloat162float(h0));
    __nv_bfloat16 l1 = __float2bfloat16(w1 - __bfloat162float(h1));

    int chunk = k >> 6, kloc = k & 63;
    int panel = n0 >> 6, nloc = n0 & 63;
    uint32_t sw = SW128((uint32_t)(kloc * 128 + nloc * 2));
    size_t ohi = ((size_t)(half * 2 + 0) * 16 + chunk) * 16384 + panel * 8192 + sw;
    size_t olo = ((size_t)(half * 2 + 1) * 16 + chunk) * 16384 + panel * 8192 + sw;

    *(__nv_bfloat162*)(g_wbf + ohi) = __halves2bfloat162(h0, h1);
    *(__nv_bfloat162*)(g_wbf + olo) = __halves2bfloat162(l0, l1);
}

// ------- prep A: gather + split into swizzled bf16 hi/lo chunk images -------
__global__ void prep_a_kernel(const float* __restrict__ lstm_out,
                              const int*   __restrict__ stack_index,
                              const int*   __restrict__ stack_len,
                              const int*   __restrict__ buffer_index,
                              const int*   __restrict__ buffer_len)
{
    int gid = blockIdx.x * blockDim.x + threadIdx.x;   // 262144
    int m   = gid >> 6;                                // 0..4095
    int kq  = (gid & 63) * 16;                         // base k (8 pairs)

    int sl = stack_len[m];
    int bl = buffer_len[m];

    #pragma unroll
    for (int p = 0; p < 8; ++p) {
        int k = kq + p * 2;
        float2 v = make_float2(0.f, 0.f);
        if (k < K_) {
            int slot = k / D_;
            int d    = k - slot * D_;
            int off  = -1;
            if (slot < 3) { if (slot < sl) off = (m * T_ + stack_index[m * 3 + slot]) * D_; }
            else          { if (0 < bl)    off = (m * T_ + buffer_index[m]) * D_; }
            if (off >= 0) v = *(const float2*)(lstm_out + off + d);
        }
        __nv_bfloat16 hx = __float2bfloat16(v.x);
        __nv_bfloat16 hy = __float2bfloat16(v.y);
        __nv_bfloat16 lx = __float2bfloat16(v.x - __bfloat162float(hx));
        __nv_bfloat16 ly = __float2bfloat16(v.y - __bfloat162float(hy));

        int chunk = k >> 6, kloc = k & 63;
        size_t base = ((size_t)((m >> 5) * 16 + chunk)) * 8192;
        uint32_t sw = SW128((uint32_t)((m & 31) * 128 + (kloc >> 1) * 4));
        *(__nv_bfloat162*)(g_abf + base + sw)        = __halves2bfloat162(hx, hy);
        *(__nv_bfloat162*)(g_abf + base + 4096 + sw) = __halves2bfloat162(lx, ly);
    }
}

// ---------------- main kernel --------------------------------------------------
__global__ __launch_bounds__(THREADS, 2)
void parser_hmma_kernel(const float* __restrict__ b1t,
                        const float* __restrict__ W2t,
                        const float* __restrict__ b2t,
                        const float* __restrict__ b1r,
                        const float* __restrict__ W2r,
                        const float* __restrict__ b2r,
                        float* __restrict__ out)
{
    extern __shared__ char smem[];
    const uint32_t sb = smem_u32(smem);
    const int tid  = threadIdx.x;
    const int wid  = tid >> 5;
    const int lane = tid & 31;
    const int wm   = wid & 1;
    const int wn   = wid >> 1;
    const int b0   = blockIdx.x * BM;
    const int half = blockIdx.y;

    // per-lane ldmatrix geometry
    const int g = lane >> 3, r8 = lane & 7;
    const int arow  = wm * 16 + (g & 1) * 8 + r8;
    const int acolk = (g >> 1) * 8;
    const int brow  = (g & 1) * 8 + r8;
    const int bcol  = ((wn * 32) & 63) + (g >> 1) * 8;
    const uint32_t bpanel = (uint32_t)(wn >> 1) * 8192;

    float acc[4][4];
    #pragma unroll
    for (int j = 0; j < 4; ++j)
        #pragma unroll
        for (int e = 0; e < 4; ++e) acc[j][e] = 0.f;

    auto fillB = [&](int c) {
        int buf = c & 1;
        uint32_t dh = sb + OFF_B + (buf * 2 + 0) * 16384;
        uint32_t dl = sb + OFF_B + (buf * 2 + 1) * 16384;
        const uint8_t* sh = g_wbf + ((size_t)(half * 2 + 0) * 16 + c) * 16384;
        const uint8_t* sl = g_wbf + ((size_t)(half * 2 + 1) * 16 + c) * 16384;
        #pragma unroll
        for (int it = 0; it < 4; ++it) {
            int o = (it * THREADS + tid) * 16;
            cp_async16(dh + o, sh + o);
            cp_async16(dl + o, sl + o);
        }
    };
    auto fillA = [&](int c) {
        int buf = c & 1;
        uint32_t d = sb + OFF_A + buf * 8192;
        const uint8_t* s = g_abf + ((size_t)(blockIdx.x * 16 + c)) * 8192;
        #pragma unroll
        for (int it = 0; it < 2; ++it) {
            int o = (it * THREADS + tid) * 16;
            cp_async16(d + o, s + o);
        }
    };

    // preamble
    fillB(0); fillA(0); cp_commit();

    for (int c = 0; c < NCHUNK; ++c) {
        __syncthreads();                         // everyone done with buffer (c+1)&1
        if (c + 1 < NCHUNK) { fillB(c + 1); fillA(c + 1); }
        cp_commit();
        cp_wait<1>();                            // group c complete (this thread)
        __syncthreads();                         // all threads' fills visible

        int buf = c & 1;
        uint32_t ah = sb + OFF_A + buf * 8192;
        uint32_t al = ah + 4096;
        uint32_t bh = sb + OFF_B + (buf * 2 + 0) * 16384 + bpanel;
        uint32_t bl = sb + OFF_B + (buf * 2 + 1) * 16384 + bpanel;

        #pragma unroll
        for (int ks = 0; ks < 4; ++ks) {
            const int kb = ks * 16;
            uint32_t Ah[4], Al[4], Bh[2][4], Bl[2][4];
            {
                uint32_t off = SW128((uint32_t)(arow * 128 + (kb + acolk) * 2));
                ldsm4(Ah, ah + off);
                ldsm4(Al, al + off);
            }
            #pragma unroll
            for (int j2 = 0; j2 < 2; ++j2) {
                uint32_t off = SW128((uint32_t)((kb + brow) * 128 + (bcol + j2 * 16) * 2));
                ldsm4t(Bh[j2], bh + off);
                ldsm4t(Bl[j2], bl + off);
            }
            // pass-major order: no back-to-back RAW on accumulators
            #pragma unroll
            for (int j = 0; j < 4; ++j) {
                int j2 = j >> 1, pp = (j & 1) * 2;
                mma16816(acc[j], Ah, Bh[j2][pp], Bh[j2][pp + 1]);
            }
            #pragma unroll
            for (int j = 0; j < 4; ++j) {
                int j2 = j >> 1, pp = (j & 1) * 2;
                mma16816(acc[j], Ah, Bl[j2][pp], Bl[j2][pp + 1]);
            }
            #pragma unroll
            for (int j = 0; j < 4; ++j) {
                int j2 = j >> 1, pp = (j & 1) * 2;
                mma16816(acc[j], Al, Bh[j2][pp], Bh[j2][pp + 1]);
            }
        }
    }
    __syncthreads();   // all compute done before smem repurpose

    // ---- epilogue: fragments -> bias + tanh -> Hs; stage W2 into smem ----
    const int NO = half ? NL : NT;
    const float* W2 = half ? W2r : W2t;
    const float* b1 = half ? b1r : b1t;
    float* Hs  = (float*)(smem + OFF_HS);    // [32][HSS]
    float* W2s = (float*)(smem + OFF_W2S);   // [H_][NO]

    #pragma unroll
    for (int j = 0; j < 4; ++j) {
        int row = wm * 16 + (lane >> 2);
        int col = wn * 32 + j * 8 + (lane & 3) * 2;
        float bv0 = (col < H_)     ? __ldg(b1 + col)     : 0.f;
        float bv1 = (col + 1 < H_) ? __ldg(b1 + col + 1) : 0.f;
        Hs[row * HSS + col]           = tanhf(acc[j][0] + bv0);
        Hs[row * HSS + col + 1]       = tanhf(acc[j][1] + bv1);
        Hs[(row + 8) * HSS + col]     = tanhf(acc[j][2] + bv0);
        Hs[(row + 8) * HSS + col + 1] = tanhf(acc[j][3] + bv1);
    }
    for (int i = tid; i < H_ * NO; i += THREADS) W2s[i] = __ldg(W2 + i);
    __syncthreads();

    // ---- tiny layer 2 + final tanh (4-way partial sums) ----
    const float* b2 = half ? b2r : b2t;
    float* obase = half ? (out + B_TOT * NT) : out;

    for (int idx = tid; idx < BM * NO; idx += THREADS) {
        int row = idx / NO;
        int o   = idx - row * NO;
        const float* hrow = Hs + row * HSS;
        float s0 = 0.f, s1 = 0.f, s2 = 0.f, s3 = 0.f;
        #pragma unroll 4
        for (int k = 0; k < 124; k += 4) {
            s0 += hrow[k]     * W2s[k * NO + o];
            s1 += hrow[k + 1] * W2s[(k + 1) * NO + o];
            s2 += hrow[k + 2] * W2s[(k + 2) * NO + o];
            s3 += hrow[k + 3] * W2s[(k + 3) * NO + o];
        }
        float s = __ldg(b2 + o) + ((s0 + s1) + (s2 + s3))
                + hrow[124] * W2s[124 * NO + o];
        obase[(b0 + row) * NO + o] = tanhf(s);
    }
}

extern "C" void kernel_launch(void* const* d_in, const int* in_sizes, int n_in,
                              void* d_out, int out_size)
{
    const float* lstm_out     = (const float*)d_in[0];
    const int*   stack_index  = (const int*)  d_in[1];
    const int*   stack_len    = (const int*)  d_in[2];
    const int*   buffer_index = (const int*)  d_in[3];
    const int*   buffer_len   = (const int*)  d_in[4];
    const float* W1t          = (const float*)d_in[5];
    const float* b1t          = (const float*)d_in[6];
    const float* W2t          = (const float*)d_in[7];
    const float* b2t          = (const float*)d_in[8];
    const float* W1r          = (const float*)d_in[9];
    const float* b1r          = (const float*)d_in[10];
    const float* W2r          = (const float*)d_in[11];
    const float* b2r          = (const float*)d_in[12];
    float* out = (float*)d_out;

    prep_w_kernel<<<512, 256>>>(W1t, W1r);
    prep_a_kernel<<<1024, 256>>>(lstm_out, stack_index, stack_len,
                                 buffer_index, buffer_len);

    cudaFuncSetAttribute(parser_hmma_kernel,
                         cudaFuncAttributeMaxDynamicSharedMemorySize, SMEM_TOTAL);
    dim3 grid(B_TOT / BM, 2);
    parser_hmma_kernel<<<grid, THREADS, SMEM_TOTAL>>>(
        b1t, W2t, b2t, b1r, W2r, b2r, out);
}